// round 14
// baseline (speedup 1.0000x reference)
#include <cuda_runtime.h>
#include <math.h>

// Problem dims (fixed by the reference)
#define Bv 32
#define Tv 128
#define Fv 64
#define Hv 64
#define BST 36           // state row stride; rows >=32 get +4 word skew (bank split)
#define WST 68           // transposed weight row stride [j][k]: conflict-free LDS.128
#define NTHREADS 512
#define STB (Hv*BST)     // one state plane: 2304 floats (skew fits exactly)

typedef unsigned long long u64;
typedef unsigned int u32;

// state row address (in floats) with bank skew for the upper k-half
#define SROW(j) ((j)*BST + (((j) >= 32) ? 4 : 0))

// ---------------------------------------------------------------------------
// Scratch (allocation-free): transposed inputs + precomputed time terms
// ---------------------------------------------------------------------------
__device__ float g_xT[Tv*Fv*Bv];   // x   -> [t][f][b]
__device__ float g_lT[Tv*Fv*Bv];   // l   -> [t][f][b]
__device__ float g_Tm[Tv*Fv*Bv];   // 1/log(t+e)
__device__ float g_sTm[Tv*Fv*Bv];  // sigmoid(Tm)
__device__ float g_fw[Tv*Bv];      // sum_f exp(-0.5*freq[b,t,f])

struct KParams { const float* p[30]; };

// ---------------------------------------------------------------------------
// Prologue: transpose + time precompute + cross-feature freq reduction
// ---------------------------------------------------------------------------
__global__ void prologue_kernel(KParams prm) {
    int b  = blockIdx.x >> 7;          // / Tv
    int t  = blockIdx.x & (Tv - 1);
    int fi = threadIdx.x;

    const float* inputs = prm.p[0];
    const float* times  = prm.p[1];
    const float* lastv  = prm.p[2];
    const float* freqs  = prm.p[3];

    int gin  = (b*Tv + t)*Fv + fi;     // [B,T,F]
    int gout = (t*Fv + fi)*Bv + b;     // [T,F,B]

    g_xT[gout] = inputs[gin];
    g_lT[gout] = lastv[gin];
    float tv = times[gin];
    float tm = 1.0f / logf(tv + 2.718281828459045f);
    g_Tm[gout]  = tm;
    g_sTm[gout] = 1.0f / (1.0f + expf(-tm));

    float e = expf(-0.5f * freqs[gin]);
    #pragma unroll
    for (int off = 16; off > 0; off >>= 1)
        e += __shfl_down_sync(0xffffffffu, e, off);
    __shared__ float red[2];
    if ((threadIdx.x & 31) == 0) red[threadIdx.x >> 5] = e;
    __syncthreads();
    if (threadIdx.x == 0) g_fw[t*Bv + b] = red[0] + red[1];
}

// ---------------------------------------------------------------------------
// Packed f32x2 helpers
// ---------------------------------------------------------------------------
__device__ __forceinline__ u64 pk2(float x) {
    u64 r; asm("mov.b64 %0, {%1, %1};" : "=l"(r) : "f"(x)); return r;
}
__device__ __forceinline__ void fma2(u64& d, u64 a, u64 b) {
    asm("fma.rn.f32x2 %0, %1, %2, %0;" : "+l"(d) : "l"(a), "l"(b));
}
__device__ __forceinline__ float2 up2(u64 v) {
    float2 r; asm("mov.b64 {%0, %1}, %2;" : "=f"(r.x), "=f"(r.y) : "l"(v)); return r;
}
__device__ __forceinline__ u64 add2(u64 a, u64 b) {
    u64 r; asm("add.rn.f32x2 %0, %1, %2;" : "=l"(r) : "l"(a), "l"(b)); return r;
}
__device__ __forceinline__ u64 shflx16(u64 v) {
    u32 lo = (u32)v, hi = (u32)(v >> 32);
    lo = __shfl_xor_sync(0xffffffffu, lo, 16);
    hi = __shfl_xor_sync(0xffffffffu, hi, 16);
    return ((u64)hi << 32) | lo;
}

// ---------------------------------------------------------------------------
// Fast-but-accurate activations (identical numerics to all prior rounds)
// ---------------------------------------------------------------------------
__device__ __forceinline__ float sigf(float x) {
    return __fdividef(1.0f, 1.0f + __expf(-x));
}
__device__ __forceinline__ float tanf_(float x) {
    float e = __expf(-2.0f * fabsf(x));
    float r = __fdividef(1.0f - e, 1.0f + e);
    return copysignf(r, x);
}
__device__ __forceinline__ float eluf(float x) {
    return x > 0.0f ? x : (__expf(x) - 1.0f);
}

// ---------------------------------------------------------------------------
// Main kernel: one CTA per (feature, direction), 512 threads (16 warps).
// Warp w: jq = w&3 (16 columns), bg = w>>2 (8 batches, b0 = 8*bg).
// Lane: kh = lane>>4 (k-half), jidx = lane&15; jcol = jq*16 + jidx.
// Each thread accumulates its k-half (32 k) of 8 matrix groups x 8 batches;
// halves combined via shfl.bfly(16) + add.f32x2 (warp-local, no barrier).
// EW ownership: 4 batches bsel = b0 + kh*4. ONE barrier per step.
// R11 fusion retained: h2[s] = h_new + lt[s] computed at end of step s-1.
// ---------------------------------------------------------------------------
#define WTF (7*Hv*WST)                       // 30464
#define PRF (19*Hv)                          // 1216
#define SMEM_FLOATS (WTF + 6*STB + PRF)      // 45504 floats = 178 KB

__global__ __launch_bounds__(NTHREADS)
void tlstm_kernel(KParams prm, float* __restrict__ out) {
    const int f    = blockIdx.x;
    const int dir  = blockIdx.y;
    const int tid  = threadIdx.x;
    const int w    = tid >> 5;
    const int lane = tid & 31;
    const int jq   = w & 3;
    const int bg   = w >> 2;
    const int kh   = lane >> 4;
    const int jidx = lane & 15;
    const int jcol = jq * 16 + jidx;
    const int b0   = bg * 8;
    const int bsel = b0 + kh * 4;
    const int kbase = kh * 32;

    extern __shared__ float sm[];
    float* wT  = sm;                     // [7][Hv*WST]
    float* sB  = sm + WTF;               // [2 parities][h|c|h2] planes
    float* pUV = sm + WTF + 6*STB;       // [19][64]

    // ---- transpose per-feature weights into smem ----
    #pragma unroll
    for (int m = 0; m < 7; m++) {
        const float* gw = prm.p[12 + m] + (size_t)f * (Hv*Hv);
        float* wm = wT + m*Hv*WST;
        for (int i = tid; i < Hv*Hv; i += NTHREADS) {
            int k = i >> 6, j = i & 63;
            wm[j*WST + k] = gw[i];
        }
    }
    // params: [0..7]=U_j,U_i,U_f,U_o,U_c,U_last,U_time,Dw ; [8..18]=Wci..b_d
    for (int i = tid; i < 19*Hv; i += NTHREADS) {
        int m = i >> 6, j = i & 63;
        pUV[m*Hv + j] = (m < 8 ? prm.p[4 + m] : prm.p[19 + (m - 8)])[f*Hv + j];
    }
    // zero parity-0 h and c planes
    for (int i = tid; i < 2*STB; i += NTHREADS) sB[i] = 0.0f;

    // ---- initial lt[0]; h2[0] = 0 + lt[0] into parity-0 plane ----
    float ltr[4];
    {
        const float Ul = prm.p[9 ][f*Hv + jcol];
        const float bl = prm.p[27][f*Hv + jcol];
        const float4 l4 = *(const float4*)&g_lT[(0*Fv + f)*Bv + bsel];
        const float lva[4] = {l4.x, l4.y, l4.z, l4.w};
        #pragma unroll
        for (int bb = 0; bb < 4; bb++) ltr[bb] = eluf(lva[bb]*Ul + bl);
        *(float4*)(sB + 2*STB + SROW(jcol) + bsel) = make_float4(ltr[0],ltr[1],ltr[2],ltr[3]);
    }
    __syncthreads();

    float creg[4] = {0.f,0.f,0.f,0.f};

    for (int s = 0; s < Tv; s++) {
        const int p  = s & 1;
        const int np = p ^ 1;
        const float* cH  = sB + p*3*STB;
        const float* cC  = cH + STB;
        const float* cH2 = cC + STB;
        float* nH  = sB + np*3*STB;
        float* nC  = nH + STB;
        float* nH2 = nC + STB;

        const int t_x   = dir ? (Tv-1-s) : s;
        const int t_tm  = dir ? (s == 0 ? 0 : Tv - s) : s;
        const int t_out = dir ? (Tv-1-s) : s;
        const int lidx  = (s + 1 < Tv) ? s + 1 : Tv - 1;   // l for NEXT step

        // ===== hoisted gmem loads (latency covered by the matmul) =====
        const float4 tm4 = *(const float4*)&g_Tm [(t_tm*Fv + f)*Bv + bsel];
        const float4 fw4 = *(const float4*)&g_fw [ s*Bv + bsel];
        const float4 xv4 = *(const float4*)&g_xT [(t_x *Fv + f)*Bv + bsel];
        const float4 st4 = *(const float4*)&g_sTm[(t_tm*Fv + f)*Bv + bsel];
        const float4 ln4 = *(const float4*)&g_lT [(lidx*Fv + f)*Bv + bsel];

        // ===== fused matmul over this thread's k-half =====
        // groups 0..5: h2@{W_j,W_i,W_f,W_o,W_c,W_d}; 6: c@W_decomp; 7: h@W_d
        u64 acc[8][4];
        #pragma unroll
        for (int g = 0; g < 8; g++)
            #pragma unroll
            for (int q = 0; q < 4; q++) acc[g][q] = 0ULL;

        const float* wcol = wT + jcol*WST + kbase;
        #pragma unroll 4
        for (int k0 = 0; k0 < 32; k0 += 4) {
            float4 wv[8];
            #pragma unroll
            for (int m = 0; m < 6; m++)
                wv[m] = *(const float4*)(wcol + m*Hv*WST + k0);
            wv[6] = *(const float4*)(wcol + 6*Hv*WST + k0);   // W_decomp
            wv[7] = *(const float4*)(wcol + 5*Hv*WST + k0);   // W_d
            #pragma unroll
            for (int kk = 0; kk < 4; kk++) {
                const int kr = SROW(kbase + k0 + kk);
                ulonglong2 au0 = *(const ulonglong2*)(cH2 + kr + b0);
                ulonglong2 au1 = *(const ulonglong2*)(cH2 + kr + b0 + 4);
                ulonglong2 cu0 = *(const ulonglong2*)(cC  + kr + b0);
                ulonglong2 cu1 = *(const ulonglong2*)(cC  + kr + b0 + 4);
                ulonglong2 hu0 = *(const ulonglong2*)(cH  + kr + b0);
                ulonglong2 hu1 = *(const ulonglong2*)(cH  + kr + b0 + 4);
                #pragma unroll
                for (int m = 0; m < 6; m++) {
                    u64 w2 = pk2(((const float*)&wv[m])[kk]);
                    fma2(acc[m][0], au0.x, w2);
                    fma2(acc[m][1], au0.y, w2);
                    fma2(acc[m][2], au1.x, w2);
                    fma2(acc[m][3], au1.y, w2);
                }
                u64 we2 = pk2(((const float*)&wv[6])[kk]);
                u64 wd2 = pk2(((const float*)&wv[7])[kk]);
                fma2(acc[6][0], cu0.x, we2); fma2(acc[6][1], cu0.y, we2);
                fma2(acc[6][2], cu1.x, we2); fma2(acc[6][3], cu1.y, we2);
                fma2(acc[7][0], hu0.x, wd2); fma2(acc[7][1], hu0.y, wd2);
                fma2(acc[7][2], hu1.x, wd2); fma2(acc[7][3], hu1.y, wd2);
            }
        }

        // ===== warp-local k-half reduction (shfl.bfly 16 + packed add) =====
        // kh0 keeps batch pairs {0,1}, sends {2,3}; kh1 keeps {2,3}, sends {0,1}.
        float am[8][4];
        #pragma unroll
        for (int g = 0; g < 8; g++) {
            u64 s0 = kh ? acc[g][0] : acc[g][2];
            u64 s1 = kh ? acc[g][1] : acc[g][3];
            u64 r0 = shflx16(s0);
            u64 r1 = shflx16(s1);
            u64 o0 = kh ? acc[g][2] : acc[g][0];
            u64 o1 = kh ? acc[g][3] : acc[g][1];
            float2 v0 = up2(add2(o0, r0));
            float2 v1 = up2(add2(o1, r1));
            am[g][0] = v0.x; am[g][1] = v0.y; am[g][2] = v1.x; am[g][3] = v1.y;
        }

        // ===== elementwise for this thread's 4 batches (bsel..+3) =====
        {
            const float tma[4] = {tm4.x, tm4.y, tm4.z, tm4.w};
            const float fwa[4] = {fw4.x, fw4.y, fw4.z, fw4.w};
            const float xva[4] = {xv4.x, xv4.y, xv4.z, xv4.w};
            const float sta[4] = {st4.x, st4.y, st4.z, st4.w};
            const float lna[4] = {ln4.x, ln4.y, ln4.z, ln4.w};

            const float Uj  = pUV[0*Hv + jcol];
            const float Ui  = pUV[1*Hv + jcol];
            const float Uf  = pUV[2*Hv + jcol];
            const float Uo  = pUV[3*Hv + jcol];
            const float Uc  = pUV[4*Hv + jcol];
            const float Ul  = pUV[5*Hv + jcol];
            const float Ut  = pUV[6*Hv + jcol];
            const float Dw  = pUV[7*Hv + jcol];
            const float Wci = pUV[8*Hv + jcol];
            const float Wcf = pUV[9*Hv + jcol];
            const float Wco = pUV[10*Hv + jcol];
            const float bj  = pUV[11*Hv + jcol];
            const float bi  = pUV[12*Hv + jcol];
            const float bf  = pUV[13*Hv + jcol];
            const float bo  = pUV[14*Hv + jcol];
            const float bc  = pUV[15*Hv + jcol];
            const float bl  = pUV[16*Hv + jcol];
            const float bt  = pUV[17*Hv + jcol];
            const float bd  = pUV[18*Hv + jcol];

            float hna[4], ltn[4];
            #pragma unroll
            for (int bb = 0; bb < 4; bb++) {
                float dst  = tanf_(am[6][bb]);
                float fd1  = sigf(fwa[bb]*Dw + am[7][bb] + bd);
                float ddec = dst * (tma[bb] * fd1);
                float c2   = ddec + (creg[bb] - dst + ddec);
                float lt   = ltr[bb];
                float jg  = tanf_(am[0][bb] + xva[bb]*Uj + bj);
                float tg  = sigf(xva[bb]*Ut + sta[bb] + bt);
                float fd2 = sigf(fwa[bb]*Dw + am[5][bb] + bd);
                float ig  = sigf(xva[bb]*Ui + am[1][bb] + c2*Wci + bi*fd2);
                float fg  = sigf(xva[bb]*Uf + am[2][bb] + c2*Wcf + bf + jg);
                float fn  = fg*tma[bb] + (1.0f - fg)*fd2;
                float cg  = tanf_(xva[bb]*Uc + am[4][bb] + bc);
                float ct  = (fn + tg)*c2 + ig*jg*tg*cg;
                float og  = sigf(xva[bb]*Uo + am[3][bb] + tg + lt + ct*Wco + bo);
                float hn  = og * tanf_(ct + lt);
                creg[bb] = ct;
                hna[bb]  = hn;
                ltn[bb]  = eluf(lna[bb]*Ul + bl);     // lt for step s+1
                out[((size_t)(t_out*Bv + bsel + bb)*Fv + f)*(2*Hv) + dir*Hv + jcol] = hn;
            }
            // store next-step state: h, c, h2 = h + lt[s+1]
            const int srow = SROW(jcol);
            *(float4*)(nH  + srow + bsel) = make_float4(hna[0],hna[1],hna[2],hna[3]);
            *(float4*)(nC  + srow + bsel) = make_float4(creg[0],creg[1],creg[2],creg[3]);
            *(float4*)(nH2 + srow + bsel) = make_float4(hna[0]+ltn[0],hna[1]+ltn[1],
                                                        hna[2]+ltn[2],hna[3]+ltn[3]);
            #pragma unroll
            for (int bb = 0; bb < 4; bb++) ltr[bb] = ltn[bb];
        }
        __syncthreads();
    }
}

// ---------------------------------------------------------------------------
// Launch
// ---------------------------------------------------------------------------
extern "C" void kernel_launch(void* const* d_in, const int* in_sizes, int n_in,
                              void* d_out, int out_size) {
    KParams prm;
    for (int i = 0; i < 30; i++) prm.p[i] = (const float*)d_in[i];

    cudaFuncSetAttribute(tlstm_kernel,
                         cudaFuncAttributeMaxDynamicSharedMemorySize,
                         SMEM_FLOATS * (int)sizeof(float));

    prologue_kernel<<<Bv*Tv, Fv>>>(prm);
    tlstm_kernel<<<dim3(Fv, 2), NTHREADS, SMEM_FLOATS * sizeof(float)>>>(
        prm, (float*)d_out);
}

// round 15
// speedup vs baseline: 1.3279x; 1.3279x over previous
#include <cuda_runtime.h>
#include <math.h>

// Problem dims (fixed by the reference)
#define Bv 32
#define Tv 128
#define Fv 64
#define Hv 64
#define BST 36           // state row stride [j][b]: conflict-free STS.128 (36 % 32 == 4)
#define WST 68           // transposed weight row stride [j][k]: conflict-free LDS.128
#define NTHREADS 256
#define STB (Hv*BST)     // one state plane: 2304 floats

typedef unsigned long long u64;

// ---------------------------------------------------------------------------
// Scratch (allocation-free): transposed inputs + precomputed time terms
// ---------------------------------------------------------------------------
__device__ float g_xT[Tv*Fv*Bv];   // x   -> [t][f][b]
__device__ float g_lT[Tv*Fv*Bv];   // l   -> [t][f][b]
__device__ float g_Tm[Tv*Fv*Bv];   // 1/log(t+e)
__device__ float g_sTm[Tv*Fv*Bv];  // sigmoid(Tm)
__device__ float g_fw[Tv*Bv];      // sum_f exp(-0.5*freq[b,t,f])

struct KParams { const float* p[30]; };

// ---------------------------------------------------------------------------
// Prologue: transpose + time precompute + cross-feature freq reduction
// ---------------------------------------------------------------------------
__global__ void prologue_kernel(KParams prm) {
    int b  = blockIdx.x >> 7;          // / Tv
    int t  = blockIdx.x & (Tv - 1);
    int fi = threadIdx.x;

    const float* inputs = prm.p[0];
    const float* times  = prm.p[1];
    const float* lastv  = prm.p[2];
    const float* freqs  = prm.p[3];

    int gin  = (b*Tv + t)*Fv + fi;     // [B,T,F]
    int gout = (t*Fv + fi)*Bv + b;     // [T,F,B]

    g_xT[gout] = inputs[gin];
    g_lT[gout] = lastv[gin];
    float tv = times[gin];
    float tm = 1.0f / logf(tv + 2.718281828459045f);
    g_Tm[gout]  = tm;
    g_sTm[gout] = 1.0f / (1.0f + expf(-tm));

    float e = expf(-0.5f * freqs[gin]);
    #pragma unroll
    for (int off = 16; off > 0; off >>= 1)
        e += __shfl_down_sync(0xffffffffu, e, off);
    __shared__ float red[2];
    if ((threadIdx.x & 31) == 0) red[threadIdx.x >> 5] = e;
    __syncthreads();
    if (threadIdx.x == 0) g_fw[t*Bv + b] = red[0] + red[1];
}

// ---------------------------------------------------------------------------
// Packed f32x2 helpers
// ---------------------------------------------------------------------------
__device__ __forceinline__ u64 pk2(float x) {
    u64 r; asm("mov.b64 %0, {%1, %1};" : "=l"(r) : "f"(x)); return r;
}
__device__ __forceinline__ void fma2(u64& d, u64 a, u64 b) {
    asm("fma.rn.f32x2 %0, %1, %2, %0;" : "+l"(d) : "l"(a), "l"(b));
}
__device__ __forceinline__ float2 up2(u64 v) {
    float2 r; asm("mov.b64 {%0, %1}, %2;" : "=f"(r.x), "=f"(r.y) : "l"(v)); return r;
}

// ---------------------------------------------------------------------------
// Fast-but-accurate activations (identical numerics to all prior rounds)
// ---------------------------------------------------------------------------
__device__ __forceinline__ float sigf(float x) {
    return __fdividef(1.0f, 1.0f + __expf(-x));
}
__device__ __forceinline__ float tanf_(float x) {
    float e = __expf(-2.0f * fabsf(x));
    float r = __fdividef(1.0f - e, 1.0f + e);
    return copysignf(r, x);
}
__device__ __forceinline__ float eluf(float x) {
    return x > 0.0f ? x : (__expf(x) - 1.0f);
}

// ---------------------------------------------------------------------------
// Main kernel: one CTA per (feature, direction), 256 threads (8 warps).
// Warp w: b-group bg = w>>1 (8 batches b0 = 8*bg), j-half = w&1.
// R15 = R11 + per-pair named barriers:
//   Batch recurrences are independent; only warps {2bg, 2bg+1} share state.
//   bar.sync(bg+1, 64) replaces __syncthreads in the step loop, letting pairs
//   drift in phase so MUFU-heavy EW of one pair overlaps FMA-heavy matmul of
//   another on the same SMSP (w and w+4 share an SMSP, different pairs).
// Ping-pong parity is per-pair safe: each pair touches only its own batch
// columns of both parities. Arithmetic identical to R11.
// ---------------------------------------------------------------------------
#define SMEM_FLOATS (7*Hv*WST + 6*STB)   // 30464 + 13824 = 44288 floats = 173 KB

__global__ __launch_bounds__(NTHREADS)
void tlstm_kernel(KParams prm, float* __restrict__ out) {
    const int f    = blockIdx.x;
    const int dir  = blockIdx.y;
    const int tid  = threadIdx.x;
    const int w    = tid >> 5;
    const int lane = tid & 31;
    const int bg   = w >> 1;
    const int b0   = bg * 8;
    const int jcol = (w & 1) * 32 + lane;
    const int barid = bg + 1;            // named barrier per warp pair

    extern __shared__ float sm[];
    float* wT = sm;                    // [7][Hv*WST] : wT[m][j*WST + k]
    float* sB = sm + 7*Hv*WST;         // [2 parities][h | c | h2], each Hv*BST

    // ---- transpose per-feature weights into smem ----
    #pragma unroll
    for (int m = 0; m < 7; m++) {
        const float* gw = prm.p[12 + m] + (size_t)f * (Hv*Hv);
        float* wm = wT + m*Hv*WST;
        for (int i = tid; i < Hv*Hv; i += NTHREADS) {
            int k = i >> 6, j = i & 63;
            wm[j*WST + k] = gw[i];
        }
    }
    // zero h and c of buffer 0
    for (int i = tid; i < 2*STB; i += NTHREADS) sB[i] = 0.0f;

    // ---- hoist per-column params (loop-invariant) into registers ----
    const float Uj  = prm.p[4 ][f*Hv + jcol];
    const float Ui  = prm.p[5 ][f*Hv + jcol];
    const float Uf  = prm.p[6 ][f*Hv + jcol];
    const float Uo  = prm.p[7 ][f*Hv + jcol];
    const float Uc  = prm.p[8 ][f*Hv + jcol];
    const float Ul  = prm.p[9 ][f*Hv + jcol];
    const float Ut  = prm.p[10][f*Hv + jcol];
    const float Dw  = prm.p[11][f*Hv + jcol];
    const float Wci = prm.p[19][f*Hv + jcol];
    const float Wcf = prm.p[20][f*Hv + jcol];
    const float Wco = prm.p[21][f*Hv + jcol];
    const float bj  = prm.p[22][f*Hv + jcol];
    const float bi  = prm.p[23][f*Hv + jcol];
    const float bf  = prm.p[24][f*Hv + jcol];
    const float bo  = prm.p[25][f*Hv + jcol];
    const float bc  = prm.p[26][f*Hv + jcol];
    const float bl  = prm.p[27][f*Hv + jcol];
    const float bt  = prm.p[28][f*Hv + jcol];
    const float bd  = prm.p[29][f*Hv + jcol];

    // ---- initial lt[0] and h2[0] = 0 + lt[0] into buffer 0 ----
    float ltr[8];
    {
        const float4 lA = *(const float4*)&g_lT[(0*Fv + f)*Bv + b0];
        const float4 lB = *(const float4*)&g_lT[(0*Fv + f)*Bv + b0 + 4];
        const float lva[8] = {lA.x,lA.y,lA.z,lA.w, lB.x,lB.y,lB.z,lB.w};
        #pragma unroll
        for (int bb = 0; bb < 8; bb++) ltr[bb] = eluf(lva[bb]*Ul + bl);
        *(float4*)(sB + 2*STB + jcol*BST + b0)     = make_float4(ltr[0],ltr[1],ltr[2],ltr[3]);
        *(float4*)(sB + 2*STB + jcol*BST + b0 + 4) = make_float4(ltr[4],ltr[5],ltr[6],ltr[7]);
    }
    __syncthreads();

    float creg[8] = {0.f,0.f,0.f,0.f,0.f,0.f,0.f,0.f};

    const float* wDd  = wT + 5*Hv*WST + jcol*WST;   // W_d row for this column
    const float* wDec = wT + 6*Hv*WST + jcol*WST;   // W_decomp row

    for (int s = 0; s < Tv; s++) {
        const int p  = s & 1;
        const int np = p ^ 1;
        const float* cH  = sB + p*3*STB;
        const float* cC  = cH + STB;
        const float* cH2 = cC + STB;
        float* nH  = sB + np*3*STB;
        float* nC  = nH + STB;
        float* nH2 = nC + STB;

        const int t_x   = dir ? (Tv-1-s) : s;
        const int t_tm  = dir ? (s == 0 ? 0 : Tv - s) : s;
        const int t_out = dir ? (Tv-1-s) : s;
        const int lidx  = (s + 1 < Tv) ? s + 1 : Tv - 1;   // l for NEXT step

        // ===== hoisted gmem loads (latency covered by the fused matmul) =====
        const float4 tmA = *(const float4*)&g_Tm [(t_tm*Fv + f)*Bv + b0];
        const float4 tmB = *(const float4*)&g_Tm [(t_tm*Fv + f)*Bv + b0 + 4];
        const float4 fwA = *(const float4*)&g_fw [ s*Bv + b0];
        const float4 fwB = *(const float4*)&g_fw [ s*Bv + b0 + 4];
        const float4 xvA = *(const float4*)&g_xT [(t_x *Fv + f)*Bv + b0];
        const float4 xvB = *(const float4*)&g_xT [(t_x *Fv + f)*Bv + b0 + 4];
        const float4 stA = *(const float4*)&g_sTm[(t_tm*Fv + f)*Bv + b0];
        const float4 stB = *(const float4*)&g_sTm[(t_tm*Fv + f)*Bv + b0 + 4];
        const float4 lnA = *(const float4*)&g_lT [(lidx*Fv + f)*Bv + b0];
        const float4 lnB = *(const float4*)&g_lT [(lidx*Fv + f)*Bv + b0 + 4];

        // ===== fused matmul: c@W_decomp, h@W_d, h2@{W_j,W_i,W_f,W_o,W_c,W_d}
        u64 aD[4] = {0ULL,0ULL,0ULL,0ULL};
        u64 aF[4] = {0ULL,0ULL,0ULL,0ULL};
        u64 acc[6][4];
        #pragma unroll
        for (int m = 0; m < 6; m++)
            #pragma unroll
            for (int q = 0; q < 4; q++) acc[m][q] = 0ULL;

        #pragma unroll 4
        for (int k0 = 0; k0 < Hv; k0 += 4) {
            float4 wv[6];
            #pragma unroll
            for (int m = 0; m < 6; m++)
                wv[m] = *(const float4*)(wT + m*Hv*WST + jcol*WST + k0);
            float4 wde = *(const float4*)(wDec + k0);
            float4 wdd = *(const float4*)(wDd  + k0);
            #pragma unroll
            for (int kk = 0; kk < 4; kk++) {
                int k = k0 + kk;
                ulonglong2 cu0 = *(const ulonglong2*)(cC  + k*BST + b0);
                ulonglong2 cu1 = *(const ulonglong2*)(cC  + k*BST + b0 + 4);
                ulonglong2 hu0 = *(const ulonglong2*)(cH  + k*BST + b0);
                ulonglong2 hu1 = *(const ulonglong2*)(cH  + k*BST + b0 + 4);
                ulonglong2 au0 = *(const ulonglong2*)(cH2 + k*BST + b0);
                ulonglong2 au1 = *(const ulonglong2*)(cH2 + k*BST + b0 + 4);
                u64 we2 = pk2(((const float*)&wde)[kk]);
                u64 wd2 = pk2(((const float*)&wdd)[kk]);
                fma2(aD[0], cu0.x, we2); fma2(aD[1], cu0.y, we2);
                fma2(aD[2], cu1.x, we2); fma2(aD[3], cu1.y, we2);
                fma2(aF[0], hu0.x, wd2); fma2(aF[1], hu0.y, wd2);
                fma2(aF[2], hu1.x, wd2); fma2(aF[3], hu1.y, wd2);
                #pragma unroll
                for (int m = 0; m < 6; m++) {
                    u64 w2 = pk2(((const float*)&wv[m])[kk]);
                    fma2(acc[m][0], au0.x, w2);
                    fma2(acc[m][1], au0.y, w2);
                    fma2(acc[m][2], au1.x, w2);
                    fma2(acc[m][3], au1.y, w2);
                }
            }
        }

        // ===== elementwise (phase-1 + phase-2 fused, formulas unchanged) ====
        {
            float tma[8], fwa[8];
            tma[0]=tmA.x; tma[1]=tmA.y; tma[2]=tmA.z; tma[3]=tmA.w;
            tma[4]=tmB.x; tma[5]=tmB.y; tma[6]=tmB.z; tma[7]=tmB.w;
            fwa[0]=fwA.x; fwa[1]=fwA.y; fwa[2]=fwA.z; fwa[3]=fwA.w;
            fwa[4]=fwB.x; fwa[5]=fwB.y; fwa[6]=fwB.z; fwa[7]=fwB.w;
            float a1a[8], a2a[8];
            #pragma unroll
            for (int q = 0; q < 4; q++) {
                float2 d = up2(aD[q]); a1a[2*q] = d.x; a1a[2*q+1] = d.y;
                float2 g = up2(aF[q]); a2a[2*q] = g.x; a2a[2*q+1] = g.y;
            }
            float c2r[8];
            #pragma unroll
            for (int bb = 0; bb < 8; bb++) {
                float dst  = tanf_(a1a[bb]);
                float fd1  = sigf(fwa[bb]*Dw + a2a[bb] + bd);
                float ddec = dst * (tma[bb] * fd1);
                c2r[bb] = ddec + (creg[bb] - dst + ddec);
            }

            const float xva[8] = {xvA.x,xvA.y,xvA.z,xvA.w, xvB.x,xvB.y,xvB.z,xvB.w};
            const float sta[8] = {stA.x,stA.y,stA.z,stA.w, stB.x,stB.y,stB.z,stB.w};
            const float lna[8] = {lnA.x,lnA.y,lnA.z,lnA.w, lnB.x,lnB.y,lnB.z,lnB.w};
            float am[6][8];
            #pragma unroll
            for (int m = 0; m < 6; m++)
                #pragma unroll
                for (int q = 0; q < 4; q++) {
                    float2 v = up2(acc[m][q]);
                    am[m][2*q] = v.x; am[m][2*q+1] = v.y;
                }
            float hna[8], ltn[8];
            #pragma unroll
            for (int bb = 0; bb < 8; bb++) {
                float c2 = c2r[bb];
                float lt = ltr[bb];
                float jg  = tanf_(am[0][bb] + xva[bb]*Uj + bj);
                float tg  = sigf(xva[bb]*Ut + sta[bb] + bt);
                float fd2 = sigf(fwa[bb]*Dw + am[5][bb] + bd);
                float ig  = sigf(xva[bb]*Ui + am[1][bb] + c2*Wci + bi*fd2);
                float fg  = sigf(xva[bb]*Uf + am[2][bb] + c2*Wcf + bf + jg);
                float fn  = fg*tma[bb] + (1.0f - fg)*fd2;
                float cg  = tanf_(xva[bb]*Uc + am[4][bb] + bc);
                float ct  = (fn + tg)*c2 + ig*jg*tg*cg;
                float og  = sigf(xva[bb]*Uo + am[3][bb] + tg + lt + ct*Wco + bo);
                float hn  = og * tanf_(ct + lt);
                creg[bb] = ct;
                hna[bb]  = hn;
                ltn[bb]  = eluf(lna[bb]*Ul + bl);     // lt for step s+1
                out[((size_t)(t_out*Bv + b0 + bb)*Fv + f)*(2*Hv) + dir*Hv + jcol] = hn;
            }
            // store next-step state: h, c, h2 = h + lt[s+1]
            *(float4*)(nH  + jcol*BST + b0)     = make_float4(hna[0],hna[1],hna[2],hna[3]);
            *(float4*)(nH  + jcol*BST + b0 + 4) = make_float4(hna[4],hna[5],hna[6],hna[7]);
            *(float4*)(nC  + jcol*BST + b0)     = make_float4(creg[0],creg[1],creg[2],creg[3]);
            *(float4*)(nC  + jcol*BST + b0 + 4) = make_float4(creg[4],creg[5],creg[6],creg[7]);
            *(float4*)(nH2 + jcol*BST + b0)     = make_float4(hna[0]+ltn[0],hna[1]+ltn[1],
                                                              hna[2]+ltn[2],hna[3]+ltn[3]);
            *(float4*)(nH2 + jcol*BST + b0 + 4) = make_float4(hna[4]+ltn[4],hna[5]+ltn[5],
                                                              hna[6]+ltn[6],hna[7]+ltn[7]);
            #pragma unroll
            for (int bb = 0; bb < 8; bb++) ltr[bb] = ltn[bb];
        }
        // per-pair named barrier: only warps {2bg, 2bg+1} (64 threads) sync
        asm volatile("bar.sync %0, %1;" :: "r"(barid), "r"(64) : "memory");
    }
}

// ---------------------------------------------------------------------------
// Launch
// ---------------------------------------------------------------------------
extern "C" void kernel_launch(void* const* d_in, const int* in_sizes, int n_in,
                              void* d_out, int out_size) {
    KParams prm;
    for (int i = 0; i < 30; i++) prm.p[i] = (const float*)d_in[i];

    cudaFuncSetAttribute(tlstm_kernel,
                         cudaFuncAttributeMaxDynamicSharedMemorySize,
                         SMEM_FLOATS * (int)sizeof(float));

    prologue_kernel<<<Bv*Tv, Fv>>>(prm);
    tlstm_kernel<<<dim3(Fv, 2), NTHREADS, SMEM_FLOATS * sizeof(float)>>>(
        prm, (float*)d_out);
}